// round 2
// baseline (speedup 1.0000x reference)
#include <cuda_runtime.h>

#define B 8
#define C 512
#define HW 4096
#define TOTAL (B*C*HW)          // 16,777,216
#define TOTAL4 (TOTAL/4)        // 4,194,304

// Scratch (device globals — no allocation allowed)
__device__ float g_text_proj[B*C];
__device__ float g_v_rgb[B*C];
__device__ float g_v_dep[B*C];
__device__ float g_rd[B*2*C];     // per b: [r(512) | d(512)]
__device__ float g_p[B*C];
__device__ float g_fused[B*C];
__device__ double g_acc[2];       // sum((r-d)^2), sum(|r-d|)

__global__ void zero_acc_kernel() {
    if (threadIdx.x < 2) g_acc[threadIdx.x] = 0.0;
}

// Y[b, off+c] = dot(X[b,:K], W[c,:K]) + bias[c], for two independent (X,W,bias,Y) sets
// block = 256 threads = 32 channels x 8 batches; grid.x = N/32, grid.y = nsets
__global__ void __launch_bounds__(256) gemv8_dual(
    const float* __restrict__ x0, const float* __restrict__ x1,
    const float* __restrict__ w0, const float* __restrict__ w1,
    const float* __restrict__ b0, const float* __restrict__ b1,
    float* __restrict__ y0, float* __restrict__ y1,
    int K, int ldY, int off0, int off1)
{
    const float* X    = blockIdx.y ? x1 : x0;
    const float* W    = blockIdx.y ? w1 : w0;
    const float* bias = blockIdx.y ? b1 : b0;
    float*       Y    = blockIdx.y ? y1 : y0;
    int          off  = blockIdx.y ? off1 : off0;

    extern __shared__ float sx[];          // [8, K]
    for (int i = threadIdx.x; i < B*K; i += blockDim.x) sx[i] = X[i];
    __syncthreads();

    int b  = threadIdx.x & 7;
    int cl = threadIdx.x >> 3;
    int c  = blockIdx.x * 32 + cl;

    const float4* w4 = reinterpret_cast<const float4*>(W + (size_t)c * K);
    const float4* x4 = reinterpret_cast<const float4*>(sx + b * K);
    int K4 = K >> 2;
    float a0 = 0.f, a1 = 0.f, a2 = 0.f, a3 = 0.f;
#pragma unroll 8
    for (int t = 0; t < K4; ++t) {
        float4 w = w4[t];
        float4 x = x4[t];
        a0 += w.x * x.x;
        a1 += w.y * x.y;
        a2 += w.z * x.z;
        a3 += w.w * x.w;
    }
    Y[b * ldY + off + c] = (a0 + a1) + (a2 + a3) + bias[c];
}

// BatchNorm over batch (spatially constant -> stats over b only) + sigmoid gate + fuse
__global__ void bn_fuse_kernel(const float* __restrict__ bn_g,
                               const float* __restrict__ bn_b)
{
    int c = threadIdx.x;            // 512 threads
    float p[B];
    float mean = 0.f;
#pragma unroll
    for (int b = 0; b < B; ++b) { p[b] = g_p[b*C + c]; mean += p[b]; }
    mean *= (1.f / B);
    float var = 0.f;
#pragma unroll
    for (int b = 0; b < B; ++b) { float d = p[b] - mean; var += d * d; }
    var *= (1.f / B);
    float rstd = rsqrtf(var + 1e-5f);
    float gg = bn_g[c], gb = bn_b[c];
#pragma unroll
    for (int b = 0; b < B; ++b) {
        float xh   = (p[b] - mean) * rstd;
        float gate = 1.f / (1.f + expf(-(gg * xh + gb)));
        float r = g_rd[b*2*C + c];
        float d = g_rd[b*2*C + C + c];
        g_fused[b*C + c] = gate * r + (1.f - gate) * d;
    }
}

// Broadcast fused over HW + both loss reductions in one HBM pass
__global__ void __launch_bounds__(256) fuse_loss_kernel(
    const float4* __restrict__ rgb, const float4* __restrict__ dep,
    float4* __restrict__ out)
{
    float s2 = 0.f, s1 = 0.f;
    int stride = gridDim.x * blockDim.x;
    for (int i = blockIdx.x * blockDim.x + threadIdx.x; i < TOTAL4; i += stride) {
        int bc  = i >> 10;              // 1024 float4 per (b,c)
        float f = g_fused[bc];
        float4 r = rgb[i];
        float4 d = dep[i];
        float dx = r.x - d.x, dy = r.y - d.y, dz = r.z - d.z, dw = r.w - d.w;
        s2 += dx*dx + dy*dy + dz*dz + dw*dw;
        s1 += fabsf(dx) + fabsf(dy) + fabsf(dz) + fabsf(dw);
        out[i] = make_float4(f, f, f, f);
    }
    // block reduction
#pragma unroll
    for (int o = 16; o > 0; o >>= 1) {
        s2 += __shfl_down_sync(0xffffffffu, s2, o);
        s1 += __shfl_down_sync(0xffffffffu, s1, o);
    }
    __shared__ float sh2[8], sh1[8];
    int w = threadIdx.x >> 5, l = threadIdx.x & 31;
    if (l == 0) { sh2[w] = s2; sh1[w] = s1; }
    __syncthreads();
    if (threadIdx.x == 0) {
        float t2 = 0.f, t1 = 0.f;
#pragma unroll
        for (int j = 0; j < 8; ++j) { t2 += sh2[j]; t1 += sh1[j]; }
        atomicAdd(&g_acc[0], (double)t2);
        atomicAdd(&g_acc[1], (double)t1);
    }
}

__global__ void finalize_kernel(float* __restrict__ out) {
    const double inv = 1.0 / (double)TOTAL;
    out[TOTAL]     = (float)(g_acc[0] * inv);   // pixel_loss
    out[TOTAL + 1] = (float)(g_acc[1] * inv);   // depth_loss
}

extern "C" void kernel_launch(void* const* d_in, const int* in_sizes, int n_in,
                              void* d_out, int out_size)
{
    const float* rgb      = (const float*)d_in[0];
    const float* dep      = (const float*)d_in[1];
    const float* text     = (const float*)d_in[2];
    const float* tp_w     = (const float*)d_in[3];
    const float* tp_b     = (const float*)d_in[4];
    const float* rgb_wqkv = (const float*)d_in[5];
    const float* rgb_bqkv = (const float*)d_in[6];
    const float* rgb_wo   = (const float*)d_in[7];
    const float* rgb_bo   = (const float*)d_in[8];
    const float* dep_wqkv = (const float*)d_in[9];
    const float* dep_bqkv = (const float*)d_in[10];
    const float* dep_wo   = (const float*)d_in[11];
    const float* dep_bo   = (const float*)d_in[12];
    const float* gate_w   = (const float*)d_in[13];
    const float* gate_b   = (const float*)d_in[14];
    const float* bn_g     = (const float*)d_in[15];
    const float* bn_b     = (const float*)d_in[16];
    float* out = (float*)d_out;

    float *tp, *vr, *vd, *rd, *pp;
    cudaGetSymbolAddress((void**)&tp, g_text_proj);
    cudaGetSymbolAddress((void**)&vr, g_v_rgb);
    cudaGetSymbolAddress((void**)&vd, g_v_dep);
    cudaGetSymbolAddress((void**)&rd, g_rd);
    cudaGetSymbolAddress((void**)&pp, g_p);

    zero_acc_kernel<<<1, 32>>>();

    // K1: text_proj = text_feat @ tp_w.T + tp_b
    gemv8_dual<<<dim3(16,1), 256, B*512*4>>>(
        text, text, tp_w, tp_w, tp_b, tp_b, tp, tp, 512, 512, 0, 0);

    // K2: v = text_proj @ Wv.T + bv  (Wv = rows [2C,3C) of wqkv), rgb & dep in parallel
    gemv8_dual<<<dim3(16,2), 256, B*512*4>>>(
        tp, tp,
        rgb_wqkv + 2*C*C, dep_wqkv + 2*C*C,
        rgb_bqkv + 2*C,   dep_bqkv + 2*C,
        vr, vd, 512, 512, 0, 0);

    // K3: r = v_rgb @ Wo_rgb.T + bo ; d = v_dep @ Wo_dep.T + bo  -> packed [r|d] per batch
    gemv8_dual<<<dim3(16,2), 256, B*512*4>>>(
        vr, vd, rgb_wo, dep_wo, rgb_bo, dep_bo,
        rd, rd, 512, 2*C, 0, C);

    // K4: p = [r|d] @ gate_w.T + gate_b
    gemv8_dual<<<dim3(16,1), 256, B*1024*4>>>(
        rd, rd, gate_w, gate_w, gate_b, gate_b, pp, pp, 1024, 512, 0, 0);

    // K5: batchnorm stats over b + sigmoid gate + fuse -> g_fused[8,512]
    bn_fuse_kernel<<<1, 512>>>(bn_g, bn_b);

    // K6: broadcast fused over HW, compute both losses (HBM-bound pass)
    fuse_loss_kernel<<<1184, 256>>>(
        (const float4*)rgb, (const float4*)dep, (float4*)out);

    // K7: write the two loss scalars
    finalize_kernel<<<1, 1>>>(out);
}

// round 3
// speedup vs baseline: 2.3381x; 2.3381x over previous
#include <cuda_runtime.h>

#define B 8
#define C 512
#define HW 4096
#define TOTAL (B*C*HW)          // 16,777,216
#define TOTAL4 (TOTAL/4)        // 4,194,304

// Scratch (device globals — no allocation allowed)
__device__ float g_text_proj[B*C];
__device__ float g_v_rgb[B*C];
__device__ float g_v_dep[B*C];
__device__ float g_rd[B*2*C];     // per b: [r(512) | d(512)]
__device__ float g_p[B*C];
__device__ float g_fused[B*C];
__device__ double g_acc[2];       // sum((r-d)^2), sum(|r-d|)
__device__ unsigned int g_count;

// Warp-per-channel GEMV: Y[b, off+c] = dot(X[b,:K], W[c,:K]) + bias[c]
// block = 256 threads = 8 warps = 8 channels; grid.x = C/8; grid.y = nsets
template<int K>
__global__ void __launch_bounds__(256) gemv8_dual(
    const float* __restrict__ x0, const float* __restrict__ x1,
    const float* __restrict__ w0, const float* __restrict__ w1,
    const float* __restrict__ b0, const float* __restrict__ b1,
    float* __restrict__ y0, float* __restrict__ y1,
    int ldY, int off0, int off1)
{
    const float* X    = blockIdx.y ? x1 : x0;
    const float* W    = blockIdx.y ? w1 : w0;
    const float* bias = blockIdx.y ? b1 : b0;
    float*       Y    = blockIdx.y ? y1 : y0;
    int          off  = blockIdx.y ? off1 : off0;

    constexpr int K4 = K >> 2;
    __shared__ float4 sx4[B * K4];
    const float4* X4 = reinterpret_cast<const float4*>(X);
    for (int i = threadIdx.x; i < B * K4; i += 256) sx4[i] = X4[i];
    __syncthreads();

    int warp = threadIdx.x >> 5, lane = threadIdx.x & 31;
    int c = blockIdx.x * 8 + warp;
    const float4* w4 = reinterpret_cast<const float4*>(W) + (size_t)c * K4;

    float acc[B];
#pragma unroll
    for (int b = 0; b < B; ++b) acc[b] = 0.f;

#pragma unroll
    for (int tt = 0; tt < K4 / 32; ++tt) {
        int t = tt * 32 + lane;
        float4 w = w4[t];
#pragma unroll
        for (int b = 0; b < B; ++b) {
            float4 x = sx4[b * K4 + t];
            acc[b] += w.x * x.x + w.y * x.y + w.z * x.z + w.w * x.w;
        }
    }
#pragma unroll
    for (int b = 0; b < B; ++b) {
#pragma unroll
        for (int o = 16; o > 0; o >>= 1)
            acc[b] += __shfl_xor_sync(0xffffffffu, acc[b], o);
    }
    if (lane == 0) {
        float bv = bias[c];
#pragma unroll
        for (int b = 0; b < B; ++b) Y[b * ldY + off + c] = acc[b] + bv;
    }
}

// BatchNorm over batch (values spatially constant -> stats over b only)
// + sigmoid gate + fuse. Also zeroes the loss accumulators for this launch.
__global__ void bn_fuse_kernel(const float* __restrict__ bn_g,
                               const float* __restrict__ bn_b)
{
    if (threadIdx.x == 0) { g_acc[0] = 0.0; g_acc[1] = 0.0; }
    int c = threadIdx.x;            // 512 threads
    float p[B];
    float mean = 0.f;
#pragma unroll
    for (int b = 0; b < B; ++b) { p[b] = g_p[b*C + c]; mean += p[b]; }
    mean *= (1.f / B);
    float var = 0.f;
#pragma unroll
    for (int b = 0; b < B; ++b) { float d = p[b] - mean; var += d * d; }
    var *= (1.f / B);
    float rstd = rsqrtf(var + 1e-5f);
    float gg = bn_g[c], gb = bn_b[c];
#pragma unroll
    for (int b = 0; b < B; ++b) {
        float xh   = (p[b] - mean) * rstd;
        float gate = 1.f / (1.f + expf(-(gg * xh + gb)));
        float r = g_rd[b*2*C + c];
        float d = g_rd[b*2*C + C + c];
        g_fused[b*C + c] = gate * r + (1.f - gate) * d;
    }
}

// Broadcast fused over HW + both loss reductions in one HBM pass.
// Last block to finish writes the two loss scalars (fused finalize).
__global__ void __launch_bounds__(256) fuse_loss_kernel(
    const float4* __restrict__ rgb, const float4* __restrict__ dep,
    float4* __restrict__ out, float* __restrict__ out_s)
{
    float s2 = 0.f, s1 = 0.f;
    int stride = gridDim.x * blockDim.x;
    for (int i = blockIdx.x * blockDim.x + threadIdx.x; i < TOTAL4; i += stride) {
        int bc  = i >> 10;              // 1024 float4 per (b,c)
        float f = g_fused[bc];
        float4 r = rgb[i];
        float4 d = dep[i];
        float dx = r.x - d.x, dy = r.y - d.y, dz = r.z - d.z, dw = r.w - d.w;
        s2 += dx*dx + dy*dy + dz*dz + dw*dw;
        s1 += fabsf(dx) + fabsf(dy) + fabsf(dz) + fabsf(dw);
        out[i] = make_float4(f, f, f, f);
    }
#pragma unroll
    for (int o = 16; o > 0; o >>= 1) {
        s2 += __shfl_down_sync(0xffffffffu, s2, o);
        s1 += __shfl_down_sync(0xffffffffu, s1, o);
    }
    __shared__ float sh2[8], sh1[8];
    int w = threadIdx.x >> 5, l = threadIdx.x & 31;
    if (l == 0) { sh2[w] = s2; sh1[w] = s1; }
    __syncthreads();
    if (threadIdx.x == 0) {
        float t2 = 0.f, t1 = 0.f;
#pragma unroll
        for (int j = 0; j < 8; ++j) { t2 += sh2[j]; t1 += sh1[j]; }
        atomicAdd(&g_acc[0], (double)t2);
        atomicAdd(&g_acc[1], (double)t1);
        __threadfence();
        unsigned int done = atomicAdd(&g_count, 1u);
        if (done == gridDim.x - 1u) {
            g_count = 0;                       // reset for next replay
            const double inv = 1.0 / (double)TOTAL;
            out_s[TOTAL]     = (float)(g_acc[0] * inv);   // pixel_loss
            out_s[TOTAL + 1] = (float)(g_acc[1] * inv);   // depth_loss
        }
    }
}

extern "C" void kernel_launch(void* const* d_in, const int* in_sizes, int n_in,
                              void* d_out, int out_size)
{
    const float* rgb      = (const float*)d_in[0];
    const float* dep      = (const float*)d_in[1];
    const float* text     = (const float*)d_in[2];
    const float* tp_w     = (const float*)d_in[3];
    const float* tp_b     = (const float*)d_in[4];
    const float* rgb_wqkv = (const float*)d_in[5];
    const float* rgb_bqkv = (const float*)d_in[6];
    const float* rgb_wo   = (const float*)d_in[7];
    const float* rgb_bo   = (const float*)d_in[8];
    const float* dep_wqkv = (const float*)d_in[9];
    const float* dep_bqkv = (const float*)d_in[10];
    const float* dep_wo   = (const float*)d_in[11];
    const float* dep_bo   = (const float*)d_in[12];
    const float* gate_w   = (const float*)d_in[13];
    const float* gate_b   = (const float*)d_in[14];
    const float* bn_g     = (const float*)d_in[15];
    const float* bn_b     = (const float*)d_in[16];
    float* out = (float*)d_out;

    float *tp, *vr, *vd, *rd, *pp;
    cudaGetSymbolAddress((void**)&tp, g_text_proj);
    cudaGetSymbolAddress((void**)&vr, g_v_rgb);
    cudaGetSymbolAddress((void**)&vd, g_v_dep);
    cudaGetSymbolAddress((void**)&rd, g_rd);
    cudaGetSymbolAddress((void**)&pp, g_p);

    // K1: text_proj = text_feat @ tp_w.T + tp_b
    gemv8_dual<512><<<dim3(64,1), 256>>>(
        text, text, tp_w, tp_w, tp_b, tp_b, tp, tp, 512, 0, 0);

    // K2: v = text_proj @ Wv.T + bv  (Wv = rows [2C,3C) of wqkv), rgb & dep in parallel
    gemv8_dual<512><<<dim3(64,2), 256>>>(
        tp, tp,
        rgb_wqkv + 2*C*C, dep_wqkv + 2*C*C,
        rgb_bqkv + 2*C,   dep_bqkv + 2*C,
        vr, vd, 512, 0, 0);

    // K3: r = v_rgb @ Wo_rgb.T + bo ; d = v_dep @ Wo_dep.T + bo -> packed [r|d] per batch
    gemv8_dual<512><<<dim3(64,2), 256>>>(
        vr, vd, rgb_wo, dep_wo, rgb_bo, dep_bo,
        rd, rd, 2*C, 0, C);

    // K4: p = [r|d] @ gate_w.T + gate_b
    gemv8_dual<1024><<<dim3(64,1), 256>>>(
        rd, rd, gate_w, gate_w, gate_b, gate_b, pp, pp, 512, 0, 0);

    // K5: batchnorm over b + sigmoid gate + fuse -> g_fused[8,512]; zeroes accumulators
    bn_fuse_kernel<<<1, 512>>>(bn_g, bn_b);

    // K6: broadcast fused over HW + both losses + finalize (last block)
    fuse_loss_kernel<<<1184, 256>>>(
        (const float4*)rgb, (const float4*)dep, (float4*)out, out);
}

// round 7
// speedup vs baseline: 2.8226x; 1.2073x over previous
#include <cuda_runtime.h>

#define B 8
#define C 512
#define HW 4096
#define TOTAL (B*C*HW)          // 16,777,216
#define TOTAL4 (TOTAL/4)        // 4,194,304
#define CHAIN_GRID 128
#define NW 8                    // warps per chain CTA

// Scratch (device globals — no allocation allowed)
__device__ float g_text_proj[B*C];
__device__ float g_v_rgb[B*C];
__device__ float g_v_dep[B*C];
__device__ float g_rd[B*2*C];     // per b: [r(512) | d(512)]
__device__ float g_p[B*C];
__device__ float g_fused[B*C];
__device__ double g_acc[2];       // sum((r-d)^2), sum(|r-d|)
__device__ unsigned int g_count;

// Grid barrier state: generation counter is monotonic across graph replays
// (no reset needed -> replay-safe).
__device__ unsigned int g_bar_cnt;
__device__ volatile unsigned int g_bar_gen;

__device__ __forceinline__ void grid_barrier() {
    __syncthreads();
    if (threadIdx.x == 0) {
        __threadfence();
        unsigned int gen = g_bar_gen;
        if (atomicAdd(&g_bar_cnt, 1u) == (unsigned)gridDim.x - 1u) {
            g_bar_cnt = 0;
            __threadfence();
            g_bar_gen = gen + 1u;
        } else {
            while (g_bar_gen == gen) __nanosleep(32);
        }
        __threadfence();
    }
    __syncthreads();
}

// Warp computes one output channel for all 8 batches from smem-staged X.
template<int K>
__device__ __forceinline__ void gemv_w(
    const float4* __restrict__ sx4, const float* __restrict__ W,
    const float* __restrict__ bias, float* __restrict__ Y,
    int ldY, int off, int c, int lane)
{
    constexpr int K4 = K / 4;
    const float4* w4 = reinterpret_cast<const float4*>(W) + (size_t)c * K4;
    float acc[B];
#pragma unroll
    for (int b = 0; b < B; ++b) acc[b] = 0.f;
#pragma unroll
    for (int i = 0; i < K4 / 32; ++i) {
        float4 w = w4[i * 32 + lane];
#pragma unroll
        for (int b = 0; b < B; ++b) {
            float4 x = sx4[b * K4 + i * 32 + lane];
            acc[b] += w.x * x.x + w.y * x.y + w.z * x.z + w.w * x.w;
        }
    }
#pragma unroll
    for (int b = 0; b < B; ++b) {
#pragma unroll
        for (int o = 16; o > 0; o >>= 1)
            acc[b] += __shfl_xor_sync(0xffffffffu, acc[b], o);
    }
    if (lane == 0) {
        float bv = bias[c];
#pragma unroll
        for (int b = 0; b < B; ++b) Y[b * ldY + off + c] = acc[b] + bv;
    }
}

// Entire chain in one persistent kernel: 4 GEMV stages + BN/gate/fuse,
// separated by device grid barriers.
__global__ void __launch_bounds__(256) chain_kernel(
    const float* __restrict__ text,
    const float* __restrict__ tp_w,   const float* __restrict__ tp_b,
    const float* __restrict__ rgb_wv, const float* __restrict__ rgb_bv,
    const float* __restrict__ dep_wv, const float* __restrict__ dep_bv,
    const float* __restrict__ rgb_wo, const float* __restrict__ rgb_bo,
    const float* __restrict__ dep_wo, const float* __restrict__ dep_bo,
    const float* __restrict__ gate_w, const float* __restrict__ gate_b,
    const float* __restrict__ bn_g,   const float* __restrict__ bn_b)
{
    __shared__ float4 sx4[2048];   // up to 32KB staged X
    int tid = threadIdx.x;
    int warp = tid >> 5, lane = tid & 31;
    int gwarp = blockIdx.x * NW + warp;

    // ---- S1: text_proj = text @ tp_w.T + tp_b  (512 ch, K=512) ----
    {
        const float4* X4 = reinterpret_cast<const float4*>(text);
        for (int i = tid; i < 1024; i += 256) sx4[i] = X4[i];
        __syncthreads();
        if (gwarp < 512) gemv_w<512>(sx4, tp_w, tp_b, g_text_proj, 512, 0, gwarp, lane);
    }
    grid_barrier();

    // ---- S2: v = text_proj @ Wv.T + bv  (rgb: warps 0-511, dep: 512-1023) ----
    {
        const float4* X4 = reinterpret_cast<const float4*>(g_text_proj);
        for (int i = tid; i < 1024; i += 256) sx4[i] = X4[i];
        __syncthreads();
        if (gwarp < 512)
            gemv_w<512>(sx4, rgb_wv, rgb_bv, g_v_rgb, 512, 0, gwarp, lane);
        else
            gemv_w<512>(sx4, dep_wv, dep_bv, g_v_dep, 512, 0, gwarp - 512, lane);
    }
    grid_barrier();

    // ---- S3: r = v_rgb @ Wo_rgb.T + bo ; d = v_dep @ Wo_dep.T + bo -> g_rd[b, r|d] ----
    {
        const float4* Xr = reinterpret_cast<const float4*>(g_v_rgb);
        const float4* Xd = reinterpret_cast<const float4*>(g_v_dep);
        for (int i = tid; i < 1024; i += 256) { sx4[i] = Xr[i]; sx4[1024 + i] = Xd[i]; }
        __syncthreads();
        if (gwarp < 512)
            gemv_w<512>(sx4, rgb_wo, rgb_bo, g_rd, 1024, 0, gwarp, lane);
        else
            gemv_w<512>(sx4 + 1024, dep_wo, dep_bo, g_rd, 1024, 512, gwarp - 512, lane);
    }
    grid_barrier();

    // ---- S4: p = [r|d] @ gate_w.T + gate_b  (512 ch, K=1024) ----
    {
        const float4* X4 = reinterpret_cast<const float4*>(g_rd);
        for (int i = tid; i < 2048; i += 256) sx4[i] = X4[i];
        __syncthreads();
        if (gwarp < 512) gemv_w<1024>(sx4, gate_w, gate_b, g_p, 512, 0, gwarp, lane);
    }
    grid_barrier();

    // ---- S5: BN over batch (spatially constant) + sigmoid gate + fuse ----
    int gthread = blockIdx.x * 256 + tid;
    if (gthread == 0) { g_acc[0] = 0.0; g_acc[1] = 0.0; }
    if (gthread < 512) {
        int c = gthread;
        float p[B];
        float mean = 0.f;
#pragma unroll
        for (int b = 0; b < B; ++b) { p[b] = g_p[b*C + c]; mean += p[b]; }
        mean *= (1.f / B);
        float var = 0.f;
#pragma unroll
        for (int b = 0; b < B; ++b) { float d = p[b] - mean; var += d * d; }
        var *= (1.f / B);
        float rstd = rsqrtf(var + 1e-5f);
        float gg = bn_g[c], gb = bn_b[c];
#pragma unroll
        for (int b = 0; b < B; ++b) {
            float xh   = (p[b] - mean) * rstd;
            float gate = 1.f / (1.f + expf(-(gg * xh + gb)));
            float r = g_rd[b*2*C + c];
            float d = g_rd[b*2*C + C + c];
            g_fused[b*C + c] = gate * r + (1.f - gate) * d;
        }
    }
}

// Broadcast fused over HW + both loss reductions in one HBM pass.
// Last block to finish writes the two loss scalars.
__global__ void __launch_bounds__(256) fuse_loss_kernel(
    const float4* __restrict__ rgb, const float4* __restrict__ dep,
    float4* __restrict__ out, float* __restrict__ out_s)
{
    float s2 = 0.f, s1 = 0.f;
    int stride = gridDim.x * blockDim.x;
    for (int i = blockIdx.x * blockDim.x + threadIdx.x; i < TOTAL4; i += stride) {
        int bc  = i >> 10;              // 1024 float4 per (b,c)
        float f = g_fused[bc];
        float4 r = rgb[i];
        float4 d = dep[i];
        float dx = r.x - d.x, dy = r.y - d.y, dz = r.z - d.z, dw = r.w - d.w;
        s2 += dx*dx + dy*dy + dz*dz + dw*dw;
        s1 += fabsf(dx) + fabsf(dy) + fabsf(dz) + fabsf(dw);
        out[i] = make_float4(f, f, f, f);
    }
#pragma unroll
    for (int o = 16; o > 0; o >>= 1) {
        s2 += __shfl_down_sync(0xffffffffu, s2, o);
        s1 += __shfl_down_sync(0xffffffffu, s1, o);
    }
    __shared__ float sh2[8], sh1[8];
    int w = threadIdx.x >> 5, l = threadIdx.x & 31;
    if (l == 0) { sh2[w] = s2; sh1[w] = s1; }
    __syncthreads();
    if (threadIdx.x == 0) {
        float t2 = 0.f, t1 = 0.f;
#pragma unroll
        for (int j = 0; j < 8; ++j) { t2 += sh2[j]; t1 += sh1[j]; }
        atomicAdd(&g_acc[0], (double)t2);
        atomicAdd(&g_acc[1], (double)t1);
        __threadfence();
        unsigned int done = atomicAdd(&g_count, 1u);
        if (done == gridDim.x - 1u) {
            g_count = 0;                       // reset for next replay
            const double inv = 1.0 / (double)TOTAL;
            out_s[TOTAL]     = (float)(g_acc[0] * inv);   // pixel_loss
            out_s[TOTAL + 1] = (float)(g_acc[1] * inv);   // depth_loss
        }
    }
}

extern "C" void kernel_launch(void* const* d_in, const int* in_sizes, int n_in,
                              void* d_out, int out_size)
{
    const float* rgb      = (const float*)d_in[0];
    const float* dep      = (const float*)d_in[1];
    const float* text     = (const float*)d_in[2];
    const float* tp_w     = (const float*)d_in[3];
    const float* tp_b     = (const float*)d_in[4];
    const float* rgb_wqkv = (const float*)d_in[5];
    const float* rgb_bqkv = (const float*)d_in[6];
    const float* rgb_wo   = (const float*)d_in[7];
    const float* rgb_bo   = (const float*)d_in[8];
    const float* dep_wqkv = (const float*)d_in[9];
    const float* dep_bqkv = (const float*)d_in[10];
    const float* dep_wo   = (const float*)d_in[11];
    const float* dep_bo   = (const float*)d_in[12];
    const float* gate_w   = (const float*)d_in[13];
    const float* gate_b   = (const float*)d_in[14];
    const float* bn_g     = (const float*)d_in[15];
    const float* bn_b     = (const float*)d_in[16];
    float* out = (float*)d_out;

    chain_kernel<<<CHAIN_GRID, 256>>>(
        text, tp_w, tp_b,
        rgb_wqkv + 2*C*C, rgb_bqkv + 2*C,
        dep_wqkv + 2*C*C, dep_bqkv + 2*C,
        rgb_wo, rgb_bo, dep_wo, dep_bo,
        gate_w, gate_b, bn_g, bn_b);

    fuse_loss_kernel<<<1184, 256>>>(
        (const float4*)rgb, (const float4*)dep, (float4*)out, out);
}